// round 1
// baseline (speedup 1.0000x reference)
#include <cuda_runtime.h>
#include <math.h>

#define BB 4
#define SS 1024
#define IN 1024
#define OUT 1024
#define NH 8
#define NE 16
#define PROJ 128
#define BT (BB*SS)        // 4096 tokens
#define RLEN (2*SS-1)     // 2047 relative positions

// ---------------- scratch (static device globals; allocation-free) ----------
__device__ float g_selval[BT*NH];
__device__ int   g_selidx[BT*NH];
__device__ float g_kv  [(size_t)BT*2*PROJ];
__device__ float g_k   [(size_t)BT*PROJ];
__device__ float g_v   [(size_t)BT*PROJ];
__device__ float g_kpos[(size_t)RLEN*PROJ];
__device__ float g_qall[(size_t)BT*NE*PROJ];      // 32 MB
__device__ float g_q   [(size_t)BB*NH*SS*PROJ];   // 16 MB
__device__ float g_P   [(size_t)BB*NH*SS*RLEN];   // 268 MB
__device__ float g_att [(size_t)BB*NH*SS*SS];     // 128 MB
__device__ float g_res [(size_t)BB*NH*SS*PROJ];   // 16 MB
__device__ float g_z   [(size_t)BT*NE*PROJ];      // 32 MB

// ---------------- generic 128x128x8 SGEMM, 256 thr, 8x8 per thread ---------
// BMODE: 0 = B row-major KxN
//        1 = B is data_to_q (E,K,128): col n -> expert n>>7, col-within n&127
//        2 = B is out_proj (E,128,N): row k -> expert k>>7, p = k&127
//        3 = B is row-major NxK (compute A @ B^T)
#define BMt 128
#define BNt 128
#define BKt 8

template<int BMODE>
__global__ __launch_bounds__(256)
void sgemm_kernel(const float* __restrict__ A, const float* __restrict__ Bm,
                  float* __restrict__ C, int M, int N, int K,
                  const float* __restrict__ scalep, int alphaMode,
                  long sA, long sB, long sC, int bShiftB, int estride)
{
    __shared__ float As[BKt][BMt+4];
    __shared__ float Bs[BKt][BNt+4];
    int bz = blockIdx.z;
    const float* Ap = A  + (long)bz * sA;
    const float* Bp = Bm + (long)(bz >> bShiftB) * sB;
    float*       Cp = C  + (long)bz * sC;
    int m0 = blockIdx.y * BMt;
    int n0 = blockIdx.x * BNt;
    int tid = threadIdx.x;
    int tx = tid & 15, ty = tid >> 4;

    float acc[8][8];
    #pragma unroll
    for (int i = 0; i < 8; i++)
        #pragma unroll
        for (int j = 0; j < 8; j++) acc[i][j] = 0.f;

    for (int k0 = 0; k0 < K; k0 += BKt) {
        // ---- A tile (128 x 8), float4 per thread, store transposed
        {
            int m  = tid >> 1;
            int kk = (tid & 1) * 4;
            float4 a4 = *reinterpret_cast<const float4*>(Ap + (long)(m0+m)*K + k0 + kk);
            As[kk+0][m] = a4.x; As[kk+1][m] = a4.y;
            As[kk+2][m] = a4.z; As[kk+3][m] = a4.w;
        }
        // ---- B tile (8 x 128)
        if (BMODE == 3) {
            int n  = tid >> 1;
            int kk = (tid & 1) * 4;
            int gn = n0 + n;
            float4 b4 = make_float4(0.f,0.f,0.f,0.f);
            if (gn < N)
                b4 = *reinterpret_cast<const float4*>(Bp + (long)gn*K + k0 + kk);
            Bs[kk+0][n] = b4.x; Bs[kk+1][n] = b4.y;
            Bs[kk+2][n] = b4.z; Bs[kk+3][n] = b4.w;
        } else {
            int kk = tid >> 5;
            int nb = (tid & 31) * 4;
            int k  = k0 + kk;
            #pragma unroll
            for (int j = 0; j < 4; j++) {
                int n = n0 + nb + j;
                float v = 0.f;
                if (n < N) {
                    if (BMODE == 0)      v = Bp[(long)k * N + n];
                    else if (BMODE == 1) v = Bp[(long)(n >> 7) * estride + (long)k * PROJ + (n & 127)];
                    else                 v = Bp[(long)(k >> 7) * estride + (long)(k & 127) * N + n];
                }
                Bs[kk][nb + j] = v;
            }
        }
        __syncthreads();

        #pragma unroll
        for (int k = 0; k < BKt; k++) {
            float a[8], b[8];
            #pragma unroll
            for (int i = 0; i < 8; i++) a[i] = As[k][ty*8 + i];
            #pragma unroll
            for (int j = 0; j < 8; j++) b[j] = Bs[k][tx*8 + j];
            #pragma unroll
            for (int i = 0; i < 8; i++)
                #pragma unroll
                for (int j = 0; j < 8; j++)
                    acc[i][j] = fmaf(a[i], b[j], acc[i][j]);
        }
        __syncthreads();
    }

    float alpha = (alphaMode == 1) ? sqrtf(scalep[0]) : 1.f;
    #pragma unroll
    for (int i = 0; i < 8; i++) {
        int m = m0 + ty*8 + i;
        #pragma unroll
        for (int j = 0; j < 8; j++) {
            int n = n0 + tx*8 + j;
            if (n < N) Cp[(long)m * N + n] = alpha * acc[i][j];
        }
    }
}

// ---------------- K1: sel = curr @ sel_dst^T, top-8, sigmoid ----------------
__global__ void sel_topk_kernel(const float* __restrict__ curr,
                                const float* __restrict__ sdst)
{
    __shared__ float srow[IN];
    __shared__ float wsum[NE][4];
    __shared__ float vals[NE];
    int bs = blockIdx.x;
    int tid = threadIdx.x;           // 128 threads
    const float* row = curr + (long)bs * IN;
    for (int i = tid; i < IN; i += 128) srow[i] = row[i];
    __syncthreads();

    float acc[NE];
    #pragma unroll
    for (int e = 0; e < NE; e++) acc[e] = 0.f;
    for (int i = tid; i < IN; i += 128) {
        float c = srow[i];
        #pragma unroll
        for (int e = 0; e < NE; e++)
            acc[e] = fmaf(c, sdst[e*IN + i], acc[e]);
    }
    int lane = tid & 31, w = tid >> 5;
    #pragma unroll
    for (int e = 0; e < NE; e++) {
        float v = acc[e];
        #pragma unroll
        for (int o = 16; o > 0; o >>= 1) v += __shfl_xor_sync(0xffffffff, v, o);
        if (lane == 0) wsum[e][w] = v;
    }
    __syncthreads();
    if (tid < NE) vals[tid] = wsum[tid][0] + wsum[tid][1] + wsum[tid][2] + wsum[tid][3];
    __syncthreads();
    if (tid == 0) {
        bool used[NE];
        #pragma unroll
        for (int e = 0; e < NE; e++) used[e] = false;
        for (int h = 0; h < NH; h++) {
            int bi = 0; float bv = -3.4e38f;
            for (int e = 0; e < NE; e++)
                if (!used[e] && vals[e] > bv) { bv = vals[e]; bi = e; }
            used[bi] = true;
            g_selidx[bs*NH + h] = bi;
            g_selval[bs*NH + h] = 1.f / (1.f + expf(-bv));
        }
    }
}

// ---------------- K2b: split kv -> k*sc, v ---------------------------------
__global__ void kv_split_kernel(const float* __restrict__ scalep)
{
    int t = blockIdx.x;              // token
    int p = threadIdx.x;             // 128
    float sc = sqrtf(scalep[0]);
    g_k[(long)t*PROJ + p] = g_kv[(long)t*2*PROJ + p] * sc;
    g_v[(long)t*PROJ + p] = g_kv[(long)t*2*PROJ + PROJ + p];
}

// ---------------- K3: k_pos[i,p] = sc * pemb[i,:] . pos_to_pk[p,:] ----------
__global__ void kpos_kernel(const float* __restrict__ ptpk,
                            const float* __restrict__ scalep)
{
    __shared__ float pe[IN];
    int i = blockIdx.x;              // 0..2046
    int tid = threadIdx.x;           // 128
    float pos = (float)i - (float)(SS - 1);
    float cst = -logf(10000.f) / (float)IN;
    for (int d = tid; d < IN; d += 128) {
        int j = d >> 1;
        float dv = expf((float)(2*j) * cst);
        float a  = pos * dv;
        pe[d] = (d & 1) ? cosf(a) : sinf(a);
    }
    __syncthreads();
    float sc = sqrtf(scalep[0]);
    int lane = tid & 31, w = tid >> 5;
    for (int p = w; p < PROJ; p += 4) {
        const float* pr = ptpk + (long)p * IN;
        float s = 0.f;
        for (int d = lane; d < IN; d += 32) s = fmaf(pe[d], pr[d], s);
        #pragma unroll
        for (int o = 16; o > 0; o >>= 1) s += __shfl_xor_sync(0xffffffff, s, o);
        if (lane == 0) g_kpos[(long)i*PROJ + p] = s * sc;
    }
}

// ---------------- K4b: gather selected experts' q ---------------------------
__global__ void qgather_kernel()
{
    int s  = blockIdx.x;
    int zh = blockIdx.y;             // b*NH + h
    int b  = zh >> 3, h = zh & 7;
    int p  = threadIdx.x;            // 128
    int e  = g_selidx[((long)(b*SS) + s)*NH + h];
    g_q[((long)zh*SS + s)*PROJ + p] =
        g_qall[(((long)(b*SS + s))*NE + e)*PROJ + p];
}

// ---------------- K7: softmax with relative-position band add ---------------
__global__ void softmax_kernel()
{
    __shared__ float red[256];
    int s = blockIdx.x, z = blockIdx.y;
    int tid = threadIdx.x;           // 256
    float* arow       = g_att + ((long)z*SS + s)*SS;
    const float* prow = g_P   + ((long)z*SS + s)*RLEN + (SS - 1 - s);

    float x[4];
    float m = -3.4e38f;
    #pragma unroll
    for (int j = 0; j < 4; j++) {
        int t = tid + j*256;
        x[j] = arow[t] + prow[t];
        m = fmaxf(m, x[j]);
    }
    red[tid] = m; __syncthreads();
    for (int o = 128; o > 0; o >>= 1) {
        if (tid < o) red[tid] = fmaxf(red[tid], red[tid + o]);
        __syncthreads();
    }
    m = red[0]; __syncthreads();

    float sum = 0.f;
    #pragma unroll
    for (int j = 0; j < 4; j++) { x[j] = expf(x[j] - m); sum += x[j]; }
    red[tid] = sum; __syncthreads();
    for (int o = 128; o > 0; o >>= 1) {
        if (tid < o) red[tid] += red[tid + o];
        __syncthreads();
    }
    float inv = 1.f / red[0];
    #pragma unroll
    for (int j = 0; j < 4; j++) arow[tid + j*256] = x[j] * inv;
}

// ---------------- K9a: build dense z (B,S,NE,PROJ) --------------------------
__global__ void zbuild_kernel()
{
    int bs  = blockIdx.x;            // token
    int tid = threadIdx.x;           // 128
    float* zrow = g_z + (long)bs*NE*PROJ;
    for (int i = tid; i < NE*PROJ; i += 128) zrow[i] = 0.f;
    __syncthreads();
    int b = bs >> 10, s = bs & 1023;
    for (int h = 0; h < NH; h++) {
        int   e = g_selidx[bs*NH + h];
        float g = g_selval[bs*NH + h];
        zrow[e*PROJ + tid] =
            g * g_res[(((long)(b*NH + h))*SS + s)*PROJ + tid];
    }
}

// ---------------- launch ----------------------------------------------------
static float* symf(const void* sym) { void* p = nullptr; cudaGetSymbolAddress(&p, sym); return (float*)p; }

extern "C" void kernel_launch(void* const* d_in, const int* in_sizes, int n_in,
                              void* d_out, int out_size)
{
    const float* curr  = (const float*)d_in[0];
    const float* attn  = (const float*)d_in[1];
    const float* dtq   = (const float*)d_in[2];
    const float* dtkv  = (const float*)d_in[3];
    const float* oproj = (const float*)d_in[4];
    const float* ptpk  = (const float*)d_in[5];
    const float* sdst  = (const float*)d_in[6];
    const float* scale = (const float*)d_in[7];
    float* out = (float*)d_out;

    float* p_kv   = symf(g_kv);
    float* p_qall = symf(g_qall);
    float* p_q    = symf(g_q);
    float* p_kpos = symf(g_kpos);
    float* p_k    = symf(g_k);
    float* p_v    = symf(g_v);
    float* p_P    = symf(g_P);
    float* p_att  = symf(g_att);
    float* p_res  = symf(g_res);
    float* p_z    = symf(g_z);

    // K1: expert selection
    sel_topk_kernel<<<BT, 128>>>(curr, sdst);

    // K2: kv = attend_to @ data_to_kv   (4096 x 256 x 1024)
    sgemm_kernel<0><<<dim3(2, 32, 1), 256>>>(attn, dtkv, p_kv,
        BT, 2*PROJ, IN, scale, 0, 0, 0, 0, 0, 0);
    kv_split_kernel<<<BT, 128>>>(scale);

    // K3: positional keys
    kpos_kernel<<<RLEN, 128>>>(ptpk, scale);

    // K4: q_all = curr @ data_to_q (expert-packed)   (4096 x 2048 x 1024), *sc
    sgemm_kernel<1><<<dim3(16, 32, 1), 256>>>(curr, dtq, p_qall,
        BT, NE*PROJ, IN, scale, 1, 0, 0, 0, 0, IN*PROJ);
    qgather_kernel<<<dim3(SS, BB*NH), 128>>>();

    // K5: P = Q @ kpos^T   per (b,h): 1024 x 2047 x 128
    sgemm_kernel<3><<<dim3(16, 8, BB*NH), 256>>>(p_q, p_kpos, p_P,
        SS, RLEN, PROJ, scale, 0, (long)SS*PROJ, 0, (long)SS*RLEN, 0, 0);

    // K6: att = Q @ K^T    per (b,h): 1024 x 1024 x 128  (K shared per b)
    sgemm_kernel<3><<<dim3(8, 8, BB*NH), 256>>>(p_q, p_k, p_att,
        SS, SS, PROJ, scale, 0, (long)SS*PROJ, (long)SS*PROJ, (long)SS*SS, 3, 0);

    // K7: softmax (adds relative-position band from P)
    softmax_kernel<<<dim3(SS, BB*NH), 256>>>();

    // K8: res = att @ V    per (b,h): 1024 x 128 x 1024  (V shared per b)
    sgemm_kernel<0><<<dim3(1, 8, BB*NH), 256>>>(p_att, p_v, p_res,
        SS, PROJ, SS, scale, 0, (long)SS*SS, (long)SS*PROJ, (long)SS*PROJ, 3, 0);

    // K9: gated combine + output projection
    zbuild_kernel<<<BT, 128>>>();
    sgemm_kernel<2><<<dim3(8, 32, 1), 256>>>(p_z, oproj, out,
        BT, OUT, NE*PROJ, scale, 0, 0, 0, 0, 0, PROJ*OUT);
}

// round 2
// speedup vs baseline: 2.9775x; 2.9775x over previous
#include <cuda_runtime.h>
#include <math.h>

#define BB 4
#define SS 1024
#define IN 1024
#define OUT 1024
#define NH 8
#define NE 16
#define PROJ 128
#define BT (BB*SS)        // 4096 tokens
#define RLEN (2*SS-1)     // 2047 relative positions

// ---------------- scratch (static device globals; allocation-free) ----------
__device__ float g_selval[BT*NH];
__device__ int   g_selidx[BT*NH];
__device__ float g_kv  [(size_t)BT*2*PROJ];
__device__ float g_k   [(size_t)BT*PROJ];
__device__ float g_v   [(size_t)BT*PROJ];
__device__ float g_pemb[(size_t)RLEN*IN];         // 8.4 MB
__device__ float g_kpos[(size_t)RLEN*PROJ];
__device__ float g_qall[(size_t)BT*NE*PROJ];      // 32 MB
__device__ float g_q   [(size_t)BB*NH*SS*PROJ];   // 16 MB
__device__ float g_P   [(size_t)BB*NH*SS*RLEN];   // 268 MB (band-only written)
__device__ float g_att [(size_t)BB*NH*SS*SS];     // 128 MB
__device__ float g_res [(size_t)BB*NH*SS*PROJ];   // 16 MB
__device__ float g_z   [(size_t)BT*NE*PROJ];      // 32 MB

// ---------------- tf32 helpers ---------------------------------------------
__device__ __forceinline__ float f2tf(float f) {
    unsigned r;
    asm("cvt.rna.tf32.f32 %0, %1;" : "=r"(r) : "f"(f));
    return __uint_as_float(r);
}

__device__ __forceinline__ void mma1688(float c[4],
                                        const float a[4], const float b[2]) {
    asm volatile(
        "mma.sync.aligned.m16n8k8.row.col.f32.tf32.tf32.f32 "
        "{%0,%1,%2,%3},{%4,%5,%6,%7},{%8,%9},{%0,%1,%2,%3};"
        : "+f"(c[0]), "+f"(c[1]), "+f"(c[2]), "+f"(c[3])
        : "r"(__float_as_uint(a[0])), "r"(__float_as_uint(a[1])),
          "r"(__float_as_uint(a[2])), "r"(__float_as_uint(a[3])),
          "r"(__float_as_uint(b[0])), "r"(__float_as_uint(b[1])));
}

// ---------------- tf32 tensor-core GEMM: 128x128 tile, BK=32, 8 warps -------
// TRANSB=0: B row-major KxN  (bmode 0 plain, 1 = data_to_q experts,
//                             2 = out_proj experts)
// TRANSB=1: B row-major NxK  (compute A @ B^T)
// diagBand: n0 += 896 - m0  (relative-position band for P)
template<int TRANSB>
__global__ __launch_bounds__(256)
void tgemm(const float* __restrict__ A, const float* __restrict__ Bm,
           float* __restrict__ C,
           int M, int N, int K, int lda, int ldb, int ldc,
           int bmode, const float* __restrict__ scalep, int alphaMode,
           long sA, long sB, long sC, int bShiftB, int diagBand)
{
    __shared__ float As[128][36];
    __shared__ float Bs[32][136];

    int bz = blockIdx.z;
    const float* Ap = A  + (long)bz * sA;
    const float* Bp = Bm + (long)(bz >> bShiftB) * sB;
    float*       Cp = C  + (long)bz * sC;
    int m0 = blockIdx.y * 128;
    int n0 = blockIdx.x * 128;
    if (diagBand) n0 += (896 - m0);

    int tid  = threadIdx.x;
    int wid  = tid >> 5, lane = tid & 31;
    int wm0  = (wid & 1) * 64;        // warp M origin within tile
    int wn0  = (wid >> 1) * 32;       // warp N origin within tile
    int lg   = lane >> 2;             // groupID
    int lt   = lane & 3;              // threadID in group

    float c[4][4][4];
    #pragma unroll
    for (int i = 0; i < 4; i++)
        #pragma unroll
        for (int j = 0; j < 4; j++)
            #pragma unroll
            for (int q = 0; q < 4; q++) c[i][j][q] = 0.f;

    for (int k0 = 0; k0 < K; k0 += 32) {
        // ---- A tile 128x32
        #pragma unroll
        for (int i = 0; i < 4; i++) {
            int m  = i * 32 + (tid >> 3);
            int kk = (tid & 7) * 4;
            float4 v = make_float4(0.f, 0.f, 0.f, 0.f);
            if (m0 + m < M)
                v = *reinterpret_cast<const float4*>(Ap + (long)(m0 + m) * lda + k0 + kk);
            float4 w = make_float4(f2tf(v.x), f2tf(v.y), f2tf(v.z), f2tf(v.w));
            *reinterpret_cast<float4*>(&As[m][kk]) = w;
        }
        // ---- B tile 32x128
        if (TRANSB == 0) {
            const float* bsrc;
            if (bmode == 0)      bsrc = Bp + (long)k0 * ldb + n0;
            else if (bmode == 1) bsrc = Bp + (long)(n0 >> 7) * (IN * PROJ) + (long)k0 * PROJ;
            else                 bsrc = Bp + (long)(k0 >> 7) * (PROJ * OUT) + (long)(k0 & 127) * OUT + n0;
            #pragma unroll
            for (int i = 0; i < 4; i++) {
                int kk = i * 8 + (tid >> 5);
                int nn = (tid & 31) * 4;
                float4 v = *reinterpret_cast<const float4*>(bsrc + (long)kk * ldb + nn);
                float4 w = make_float4(f2tf(v.x), f2tf(v.y), f2tf(v.z), f2tf(v.w));
                *reinterpret_cast<float4*>(&Bs[kk][nn]) = w;
            }
        } else {
            #pragma unroll
            for (int i = 0; i < 4; i++) {
                int nn = i * 32 + (tid >> 3);
                int kk = (tid & 7) * 4;
                float4 v = make_float4(0.f, 0.f, 0.f, 0.f);
                if (n0 + nn < N)
                    v = *reinterpret_cast<const float4*>(Bp + (long)(n0 + nn) * ldb + k0 + kk);
                Bs[kk + 0][nn] = f2tf(v.x);
                Bs[kk + 1][nn] = f2tf(v.y);
                Bs[kk + 2][nn] = f2tf(v.z);
                Bs[kk + 3][nn] = f2tf(v.w);
            }
        }
        __syncthreads();

        #pragma unroll
        for (int ks = 0; ks < 4; ks++) {
            int kb = ks * 8;
            float a[4][4], b[4][2];
            #pragma unroll
            for (int mt = 0; mt < 4; mt++) {
                int r = wm0 + mt * 16 + lg;
                a[mt][0] = As[r][kb + lt];
                a[mt][1] = As[r + 8][kb + lt];
                a[mt][2] = As[r][kb + 4 + lt];
                a[mt][3] = As[r + 8][kb + 4 + lt];
            }
            #pragma unroll
            for (int nt = 0; nt < 4; nt++) {
                int cn = wn0 + nt * 8 + lg;
                b[nt][0] = Bs[kb + lt][cn];
                b[nt][1] = Bs[kb + 4 + lt][cn];
            }
            #pragma unroll
            for (int mt = 0; mt < 4; mt++)
                #pragma unroll
                for (int nt = 0; nt < 4; nt++)
                    mma1688(c[mt][nt], a[mt], b[nt]);
        }
        __syncthreads();
    }

    float alpha = alphaMode ? sqrtf(scalep[0]) : 1.f;
    #pragma unroll
    for (int mt = 0; mt < 4; mt++) {
        #pragma unroll
        for (int nt = 0; nt < 4; nt++) {
            int r  = m0 + wm0 + mt * 16 + lg;
            int cc = n0 + wn0 + nt * 8 + 2 * lt;
            if (r < M) {
                if (cc     < N) Cp[(long)r * ldc + cc]     = alpha * c[mt][nt][0];
                if (cc + 1 < N) Cp[(long)r * ldc + cc + 1] = alpha * c[mt][nt][1];
            }
            if (r + 8 < M) {
                if (cc     < N) Cp[(long)(r + 8) * ldc + cc]     = alpha * c[mt][nt][2];
                if (cc + 1 < N) Cp[(long)(r + 8) * ldc + cc + 1] = alpha * c[mt][nt][3];
            }
        }
    }
}

// ---------------- K1: sel = curr @ sel_dst^T, top-8, sigmoid ----------------
__global__ void sel_topk_kernel(const float* __restrict__ curr,
                                const float* __restrict__ sdst)
{
    __shared__ float srow[IN];
    __shared__ float wsum[NE][4];
    __shared__ float vals[NE];
    int bs = blockIdx.x;
    int tid = threadIdx.x;           // 128 threads
    const float* row = curr + (long)bs * IN;
    for (int i = tid; i < IN; i += 128) srow[i] = row[i];
    __syncthreads();

    float acc[NE];
    #pragma unroll
    for (int e = 0; e < NE; e++) acc[e] = 0.f;
    for (int i = tid; i < IN; i += 128) {
        float c = srow[i];
        #pragma unroll
        for (int e = 0; e < NE; e++)
            acc[e] = fmaf(c, sdst[e*IN + i], acc[e]);
    }
    int lane = tid & 31, w = tid >> 5;
    #pragma unroll
    for (int e = 0; e < NE; e++) {
        float v = acc[e];
        #pragma unroll
        for (int o = 16; o > 0; o >>= 1) v += __shfl_xor_sync(0xffffffff, v, o);
        if (lane == 0) wsum[e][w] = v;
    }
    __syncthreads();
    if (tid < NE) vals[tid] = wsum[tid][0] + wsum[tid][1] + wsum[tid][2] + wsum[tid][3];
    __syncthreads();
    if (tid == 0) {
        bool used[NE];
        #pragma unroll
        for (int e = 0; e < NE; e++) used[e] = false;
        for (int h = 0; h < NH; h++) {
            int bi = 0; float bv = -3.4e38f;
            for (int e = 0; e < NE; e++)
                if (!used[e] && vals[e] > bv) { bv = vals[e]; bi = e; }
            used[bi] = true;
            g_selidx[bs*NH + h] = bi;
            g_selval[bs*NH + h] = 1.f / (1.f + expf(-bv));
        }
    }
}

// ---------------- K2b: split kv -> k*sc, v ---------------------------------
__global__ void kv_split_kernel(const float* __restrict__ scalep)
{
    int t = blockIdx.x;              // token
    int p = threadIdx.x;             // 128
    float sc = sqrtf(scalep[0]);
    g_k[(long)t*PROJ + p] = g_kv[(long)t*2*PROJ + p] * sc;
    g_v[(long)t*PROJ + p] = g_kv[(long)t*2*PROJ + PROJ + p];
}

// ---------------- pemb: sinusoidal embedding materialization ----------------
__global__ void pemb_kernel()
{
    int i = blockIdx.x;              // 0..2046
    int tid = threadIdx.x;           // 256
    float pos = (float)i - (float)(SS - 1);
    float cst = -logf(10000.f) / (float)IN;
    for (int j = tid; j < IN/2; j += 256) {
        float dv = expf((float)(2*j) * cst);
        float s, co;
        sincosf(pos * dv, &s, &co);
        g_pemb[(long)i*IN + 2*j]     = s;
        g_pemb[(long)i*IN + 2*j + 1] = co;
    }
}

// ---------------- K4b: gather selected experts' q ---------------------------
__global__ void qgather_kernel()
{
    int s  = blockIdx.x;
    int zh = blockIdx.y;             // b*NH + h
    int b  = zh >> 3, h = zh & 7;
    int p  = threadIdx.x;            // 128
    int e  = g_selidx[((long)(b*SS) + s)*NH + h];
    g_q[((long)zh*SS + s)*PROJ + p] =
        g_qall[(((long)(b*SS + s))*NE + e)*PROJ + p];
}

// ---------------- K7: softmax with relative-position band add ---------------
__global__ void softmax_kernel()
{
    __shared__ float red[256];
    int s = blockIdx.x, z = blockIdx.y;
    int tid = threadIdx.x;           // 256
    float* arow       = g_att + ((long)z*SS + s)*SS;
    const float* prow = g_P   + ((long)z*SS + s)*RLEN + (SS - 1 - s);

    float x[4];
    float m = -3.4e38f;
    #pragma unroll
    for (int j = 0; j < 4; j++) {
        int t = tid + j*256;
        x[j] = arow[t] + prow[t];
        m = fmaxf(m, x[j]);
    }
    red[tid] = m; __syncthreads();
    for (int o = 128; o > 0; o >>= 1) {
        if (tid < o) red[tid] = fmaxf(red[tid], red[tid + o]);
        __syncthreads();
    }
    m = red[0]; __syncthreads();

    float sum = 0.f;
    #pragma unroll
    for (int j = 0; j < 4; j++) { x[j] = expf(x[j] - m); sum += x[j]; }
    red[tid] = sum; __syncthreads();
    for (int o = 128; o > 0; o >>= 1) {
        if (tid < o) red[tid] += red[tid + o];
        __syncthreads();
    }
    float inv = 1.f / red[0];
    #pragma unroll
    for (int j = 0; j < 4; j++) arow[tid + j*256] = x[j] * inv;
}

// ---------------- K9a: build dense z (B,S,NE,PROJ) --------------------------
__global__ void zbuild_kernel()
{
    int bs  = blockIdx.x;            // token
    int tid = threadIdx.x;           // 128
    float* zrow = g_z + (long)bs*NE*PROJ;
    for (int i = tid; i < NE*PROJ; i += 128) zrow[i] = 0.f;
    __syncthreads();
    int b = bs >> 10, s = bs & 1023;
    for (int h = 0; h < NH; h++) {
        int   e = g_selidx[bs*NH + h];
        float g = g_selval[bs*NH + h];
        zrow[e*PROJ + tid] =
            g * g_res[(((long)(b*NH + h))*SS + s)*PROJ + tid];
    }
}

// ---------------- launch ----------------------------------------------------
static float* symf(const void* sym) { void* p = nullptr; cudaGetSymbolAddress(&p, sym); return (float*)p; }

extern "C" void kernel_launch(void* const* d_in, const int* in_sizes, int n_in,
                              void* d_out, int out_size)
{
    const float* curr  = (const float*)d_in[0];
    const float* attn  = (const float*)d_in[1];
    const float* dtq   = (const float*)d_in[2];
    const float* dtkv  = (const float*)d_in[3];
    const float* oproj = (const float*)d_in[4];
    const float* ptpk  = (const float*)d_in[5];
    const float* sdst  = (const float*)d_in[6];
    const float* scale = (const float*)d_in[7];
    float* out = (float*)d_out;

    float* p_kv   = symf(g_kv);
    float* p_pemb = symf(g_pemb);
    float* p_qall = symf(g_qall);
    float* p_q    = symf(g_q);
    float* p_kpos = symf(g_kpos);
    float* p_k    = symf(g_k);
    float* p_v    = symf(g_v);
    float* p_P    = symf(g_P);
    float* p_att  = symf(g_att);
    float* p_res  = symf(g_res);
    float* p_z    = symf(g_z);

    // K1: expert selection
    sel_topk_kernel<<<BT, 128>>>(curr, sdst);

    // positional embedding + k_pos = pemb @ pos_to_pk^T * sc
    pemb_kernel<<<RLEN, 256>>>();
    tgemm<1><<<dim3(1, 16, 1), 256>>>(p_pemb, ptpk, p_kpos,
        RLEN, PROJ, IN, IN, IN, PROJ, 0, scale, 1, 0, 0, 0, 0, 0);

    // kv = attend_to @ data_to_kv
    tgemm<0><<<dim3(2, 32, 1), 256>>>(attn, dtkv, p_kv,
        BT, 2*PROJ, IN, IN, 2*PROJ, 2*PROJ, 0, scale, 0, 0, 0, 0, 0, 0);
    kv_split_kernel<<<BT, 128>>>(scale);

    // q_all = curr @ data_to_q (expert-packed), * sc
    tgemm<0><<<dim3(16, 32, 1), 256>>>(curr, dtq, p_qall,
        BT, NE*PROJ, IN, IN, PROJ, NE*PROJ, 1, scale, 1, 0, 0, 0, 0, 0);
    qgather_kernel<<<dim3(SS, BB*NH), 128>>>();

    // P band = Q @ kpos^T  (only the diagonal band used by shift)
    tgemm<1><<<dim3(9, 8, BB*NH), 256>>>(p_q, p_kpos, p_P,
        SS, RLEN, PROJ, PROJ, PROJ, RLEN, 0, scale, 0,
        (long)SS*PROJ, 0, (long)SS*RLEN, 0, 1);

    // att = Q @ K^T
    tgemm<1><<<dim3(8, 8, BB*NH), 256>>>(p_q, p_k, p_att,
        SS, SS, PROJ, PROJ, PROJ, SS, 0, scale, 0,
        (long)SS*PROJ, (long)SS*PROJ, (long)SS*SS, 3, 0);

    // softmax (adds relative-position band from P)
    softmax_kernel<<<dim3(SS, BB*NH), 256>>>();

    // res = att @ V
    tgemm<0><<<dim3(1, 8, BB*NH), 256>>>(p_att, p_v, p_res,
        SS, PROJ, SS, SS, PROJ, PROJ, 0, scale, 0,
        (long)SS*SS, (long)SS*PROJ, (long)SS*PROJ, 3, 0);

    // gated combine + output projection
    zbuild_kernel<<<BT, 128>>>();
    tgemm<0><<<dim3(8, 32, 1), 256>>>(p_z, oproj, out,
        BT, OUT, NE*PROJ, NE*PROJ, OUT, OUT, 2, scale, 0, 0, 0, 0, 0, 0);
}

// round 3
// speedup vs baseline: 3.0434x; 1.0221x over previous
#include <cuda_runtime.h>
#include <math.h>

#define BB 4
#define SS 1024
#define IN 1024
#define OUT 1024
#define NH 8
#define NE 16
#define PROJ 128
#define BT (BB*SS)        // 4096 tokens
#define RLEN (2*SS-1)     // 2047 relative positions

// ---------------- scratch (static device globals; allocation-free) ----------
__device__ float g_selval[BT*NH];
__device__ int   g_selidx[BT*NH];
__device__ float g_kv  [(size_t)BT*2*PROJ];
__device__ float g_k   [(size_t)BT*PROJ];
__device__ float g_v   [(size_t)BT*PROJ];
__device__ float g_pemb[(size_t)RLEN*IN];
__device__ float g_kpos[(size_t)RLEN*PROJ];
__device__ float g_qall[(size_t)BT*NE*PROJ];
__device__ float g_q   [(size_t)BB*NH*SS*PROJ];
__device__ float g_P   [(size_t)BB*NH*SS*RLEN];   // band-only written
__device__ float g_z   [(size_t)BT*NE*PROJ];

// ---------------- tf32 helpers ---------------------------------------------
__device__ __forceinline__ float f2tf(float f) {
    unsigned r;
    asm("cvt.rna.tf32.f32 %0, %1;" : "=r"(r) : "f"(f));
    return __uint_as_float(r);
}

__device__ __forceinline__ void mma1688(float c[4],
                                        const float a[4], const float b[2]) {
    asm volatile(
        "mma.sync.aligned.m16n8k8.row.col.f32.tf32.tf32.f32 "
        "{%0,%1,%2,%3},{%4,%5,%6,%7},{%8,%9},{%0,%1,%2,%3};"
        : "+f"(c[0]), "+f"(c[1]), "+f"(c[2]), "+f"(c[3])
        : "r"(__float_as_uint(a[0])), "r"(__float_as_uint(a[1])),
          "r"(__float_as_uint(a[2])), "r"(__float_as_uint(a[3])),
          "r"(__float_as_uint(b[0])), "r"(__float_as_uint(b[1])));
}

// ---------------- tf32 tensor-core GEMM with register prefetch --------------
template<int TRANSB>
__global__ __launch_bounds__(256)
void tgemm(const float* __restrict__ A, const float* __restrict__ Bm,
           float* __restrict__ C,
           int M, int N, int K, int lda, int ldb, int ldc,
           int bmode, const float* __restrict__ scalep, int alphaMode,
           long sA, long sB, long sC, int bShiftB, int diagBand)
{
    __shared__ float As[128][36];
    __shared__ float Bs[32][136];

    int bz = blockIdx.z;
    const float* Ap = A  + (long)bz * sA;
    const float* Bp = Bm + (long)(bz >> bShiftB) * sB;
    float*       Cp = C  + (long)bz * sC;
    int m0 = blockIdx.y * 128;
    int n0 = blockIdx.x * 128;
    if (diagBand) n0 += (896 - m0);

    int tid  = threadIdx.x;
    int wid  = tid >> 5, lane = tid & 31;
    int wm0  = (wid & 1) * 64;
    int wn0  = (wid >> 1) * 32;
    int lg   = lane >> 2;
    int lt   = lane & 3;

    float c[4][4][4];
    #pragma unroll
    for (int i = 0; i < 4; i++)
        #pragma unroll
        for (int j = 0; j < 4; j++)
            #pragma unroll
            for (int q = 0; q < 4; q++) c[i][j][q] = 0.f;

    float4 ra[4], rb[4];

    auto ldA = [&](int k0) {
        #pragma unroll
        for (int i = 0; i < 4; i++) {
            int m  = i * 32 + (tid >> 3);
            int kk = (tid & 7) * 4;
            ra[i] = make_float4(0.f, 0.f, 0.f, 0.f);
            if (m0 + m < M)
                ra[i] = *reinterpret_cast<const float4*>(Ap + (long)(m0 + m) * lda + k0 + kk);
        }
    };
    auto ldB = [&](int k0) {
        if (TRANSB == 0) {
            const float* bsrc;
            if (bmode == 0)      bsrc = Bp + (long)k0 * ldb + n0;
            else if (bmode == 1) bsrc = Bp + (long)(n0 >> 7) * (IN * PROJ) + (long)k0 * PROJ;
            else                 bsrc = Bp + (long)(k0 >> 7) * (PROJ * OUT) + (long)(k0 & 127) * OUT + n0;
            #pragma unroll
            for (int i = 0; i < 4; i++) {
                int kk = i * 8 + (tid >> 5);
                int nn = (tid & 31) * 4;
                rb[i] = *reinterpret_cast<const float4*>(bsrc + (long)kk * ldb + nn);
            }
        } else {
            #pragma unroll
            for (int i = 0; i < 4; i++) {
                int nn = i * 32 + (tid >> 3);
                int kk = (tid & 7) * 4;
                rb[i] = make_float4(0.f, 0.f, 0.f, 0.f);
                if (n0 + nn < N)
                    rb[i] = *reinterpret_cast<const float4*>(Bp + (long)(n0 + nn) * ldb + k0 + kk);
            }
        }
    };
    auto stAB = [&]() {
        #pragma unroll
        for (int i = 0; i < 4; i++) {
            int m  = i * 32 + (tid >> 3);
            int kk = (tid & 7) * 4;
            float4 w = make_float4(f2tf(ra[i].x), f2tf(ra[i].y), f2tf(ra[i].z), f2tf(ra[i].w));
            *reinterpret_cast<float4*>(&As[m][kk]) = w;
        }
        if (TRANSB == 0) {
            #pragma unroll
            for (int i = 0; i < 4; i++) {
                int kk = i * 8 + (tid >> 5);
                int nn = (tid & 31) * 4;
                float4 w = make_float4(f2tf(rb[i].x), f2tf(rb[i].y), f2tf(rb[i].z), f2tf(rb[i].w));
                *reinterpret_cast<float4*>(&Bs[kk][nn]) = w;
            }
        } else {
            #pragma unroll
            for (int i = 0; i < 4; i++) {
                int nn = i * 32 + (tid >> 3);
                int kk = (tid & 7) * 4;
                Bs[kk + 0][nn] = f2tf(rb[i].x);
                Bs[kk + 1][nn] = f2tf(rb[i].y);
                Bs[kk + 2][nn] = f2tf(rb[i].z);
                Bs[kk + 3][nn] = f2tf(rb[i].w);
            }
        }
    };

    int nk = K / 32;
    ldA(0); ldB(0);
    for (int ki = 0; ki < nk; ki++) {
        stAB();
        __syncthreads();
        if (ki + 1 < nk) { ldA((ki + 1) * 32); ldB((ki + 1) * 32); }

        #pragma unroll
        for (int ks = 0; ks < 4; ks++) {
            int kb = ks * 8;
            float a[4][4], b[4][2];
            #pragma unroll
            for (int mt = 0; mt < 4; mt++) {
                int r = wm0 + mt * 16 + lg;
                a[mt][0] = As[r][kb + lt];
                a[mt][1] = As[r + 8][kb + lt];
                a[mt][2] = As[r][kb + 4 + lt];
                a[mt][3] = As[r + 8][kb + 4 + lt];
            }
            #pragma unroll
            for (int nt = 0; nt < 4; nt++) {
                int cn = wn0 + nt * 8 + lg;
                b[nt][0] = Bs[kb + lt][cn];
                b[nt][1] = Bs[kb + 4 + lt][cn];
            }
            #pragma unroll
            for (int mt = 0; mt < 4; mt++)
                #pragma unroll
                for (int nt = 0; nt < 4; nt++)
                    mma1688(c[mt][nt], a[mt], b[nt]);
        }
        __syncthreads();
    }

    float alpha = alphaMode ? sqrtf(scalep[0]) : 1.f;
    #pragma unroll
    for (int mt = 0; mt < 4; mt++) {
        #pragma unroll
        for (int nt = 0; nt < 4; nt++) {
            int r  = m0 + wm0 + mt * 16 + lg;
            int cc = n0 + wn0 + nt * 8 + 2 * lt;
            if (r < M) {
                if (cc     < N) Cp[(long)r * ldc + cc]     = alpha * c[mt][nt][0];
                if (cc + 1 < N) Cp[(long)r * ldc + cc + 1] = alpha * c[mt][nt][1];
            }
            if (r + 8 < M) {
                if (cc     < N) Cp[(long)(r + 8) * ldc + cc]     = alpha * c[mt][nt][2];
                if (cc + 1 < N) Cp[(long)(r + 8) * ldc + cc + 1] = alpha * c[mt][nt][3];
            }
        }
    }
}

// ---------------- fused flash attention -------------------------------------
// per CTA: (zh = b*8+h, s-tile of 64). Computes softmax(QK^T + Pband) @ V,
// applies gate, scatters into g_z[token, e, :].
__global__ __launch_bounds__(256)
void flash_kernel()
{
    extern __shared__ float sm[];
    float* Qs   = sm;                    // 64 x 132
    float* Ps   = Qs + 64 * 132;         // 64 x 132
    float* Kt   = Ps + 64 * 132;         // 128 x 132  (K[t][p])
    float* Vt   = Kt + 128 * 132;        // 128 x 136  (V[t][p])
    float* redm = Vt + 128 * 136;        // 64 x 4
    float* reds = redm + 256;            // 64 x 4

    int zh = blockIdx.y;
    int b  = zh >> 3, h = zh & 7;
    int s0 = blockIdx.x * 64;
    int tid = threadIdx.x;
    int wid = tid >> 5, lane = tid & 31;
    int lg = lane >> 2, lt = lane & 3;
    int wm0 = (wid & 1) * 32;
    int wn0 = (wid >> 1) * 32;

    // load Q tile (64 x 128), already scaled & gathered
    {
        const float* qbase = g_q + (size_t)(zh * SS + s0) * PROJ;
        #pragma unroll
        for (int it = 0; it < 8; it++) {
            int lin = it * 256 + tid;
            int r = lin >> 5, cc = (lin & 31) * 4;
            float4 v = *reinterpret_cast<const float4*>(qbase + (size_t)r * PROJ + cc);
            float4 w = make_float4(f2tf(v.x), f2tf(v.y), f2tf(v.z), f2tf(v.w));
            *reinterpret_cast<float4*>(&Qs[r * 132 + cc]) = w;
        }
    }

    float o[2][4][4];
    float mrow[2][2], lrow[2][2];
    #pragma unroll
    for (int mt = 0; mt < 2; mt++) {
        mrow[mt][0] = mrow[mt][1] = -1e30f;
        lrow[mt][0] = lrow[mt][1] = 0.f;
        #pragma unroll
        for (int nt = 0; nt < 4; nt++)
            #pragma unroll
            for (int q = 0; q < 4; q++) o[mt][nt][q] = 0.f;
    }

    for (int kt = 0; kt < 8; kt++) {
        int t0  = kt * 128;
        int bt0 = b * SS + t0;
        // load K,V tiles (128 x 128)
        #pragma unroll
        for (int it = 0; it < 16; it++) {
            int lin = it * 256 + tid;
            int r = lin >> 5, cc = (lin & 31) * 4;
            float4 kv4 = *reinterpret_cast<const float4*>(g_k + (size_t)(bt0 + r) * PROJ + cc);
            float4 vv4 = *reinterpret_cast<const float4*>(g_v + (size_t)(bt0 + r) * PROJ + cc);
            *reinterpret_cast<float4*>(&Kt[r * 132 + cc]) =
                make_float4(f2tf(kv4.x), f2tf(kv4.y), f2tf(kv4.z), f2tf(kv4.w));
            *reinterpret_cast<float4*>(&Vt[r * 136 + cc]) =
                make_float4(f2tf(vv4.x), f2tf(vv4.y), f2tf(vv4.z), f2tf(vv4.w));
        }
        __syncthreads();

        // S = Q K^T
        float s_[2][4][4];
        #pragma unroll
        for (int mt = 0; mt < 2; mt++)
            #pragma unroll
            for (int nt = 0; nt < 4; nt++)
                #pragma unroll
                for (int q = 0; q < 4; q++) s_[mt][nt][q] = 0.f;
        #pragma unroll
        for (int ks = 0; ks < 16; ks++) {
            int kb = ks * 8;
            float a[2][4], bf[4][2];
            #pragma unroll
            for (int mt = 0; mt < 2; mt++) {
                int r = wm0 + mt * 16 + lg;
                a[mt][0] = Qs[r * 132 + kb + lt];
                a[mt][1] = Qs[(r + 8) * 132 + kb + lt];
                a[mt][2] = Qs[r * 132 + kb + 4 + lt];
                a[mt][3] = Qs[(r + 8) * 132 + kb + 4 + lt];
            }
            #pragma unroll
            for (int nt = 0; nt < 4; nt++) {
                int cn = wn0 + nt * 8 + lg;
                bf[nt][0] = Kt[cn * 132 + kb + lt];
                bf[nt][1] = Kt[cn * 132 + kb + 4 + lt];
            }
            #pragma unroll
            for (int mt = 0; mt < 2; mt++)
                #pragma unroll
                for (int nt = 0; nt < 4; nt++)
                    mma1688(s_[mt][nt], a[mt], bf[nt]);
        }

        // add relative-position band from g_P
        #pragma unroll
        for (int mt = 0; mt < 2; mt++) {
            #pragma unroll
            for (int ri = 0; ri < 2; ri++) {
                int srow = s0 + wm0 + mt * 16 + lg + ri * 8;
                const float* prow = g_P + (size_t)(zh * SS + srow) * RLEN + (1023 - srow) + t0;
                #pragma unroll
                for (int nt = 0; nt < 4; nt++) {
                    int c0 = wn0 + nt * 8 + 2 * lt;
                    s_[mt][nt][ri * 2 + 0] += prow[c0];
                    s_[mt][nt][ri * 2 + 1] += prow[c0 + 1];
                }
            }
        }

        // row max (warp partial -> smem -> combine)
        float pmax[2][2];
        #pragma unroll
        for (int mt = 0; mt < 2; mt++) {
            #pragma unroll
            for (int ri = 0; ri < 2; ri++) {
                float v = -1e30f;
                #pragma unroll
                for (int nt = 0; nt < 4; nt++)
                    v = fmaxf(v, fmaxf(s_[mt][nt][ri * 2], s_[mt][nt][ri * 2 + 1]));
                v = fmaxf(v, __shfl_xor_sync(0xffffffff, v, 1));
                v = fmaxf(v, __shfl_xor_sync(0xffffffff, v, 2));
                pmax[mt][ri] = v;
                if (lt == 0) {
                    int rl = wm0 + mt * 16 + lg + ri * 8;
                    redm[rl * 4 + (wid >> 1)] = v;
                }
            }
        }
        __syncthreads();

        float scl[2][2];
        #pragma unroll
        for (int mt = 0; mt < 2; mt++) {
            #pragma unroll
            for (int ri = 0; ri < 2; ri++) {
                int rl = wm0 + mt * 16 + lg + ri * 8;
                float v = fmaxf(fmaxf(redm[rl * 4 + 0], redm[rl * 4 + 1]),
                                fmaxf(redm[rl * 4 + 2], redm[rl * 4 + 3]));
                float mnew = fmaxf(mrow[mt][ri], v);
                scl[mt][ri] = expf(mrow[mt][ri] - mnew);
                mrow[mt][ri] = mnew;
            }
        }

        // exponentiate, partial row sums, rescale O, stage P into smem
        #pragma unroll
        for (int mt = 0; mt < 2; mt++) {
            #pragma unroll
            for (int ri = 0; ri < 2; ri++) {
                float m = mrow[mt][ri];
                float sum = 0.f;
                int r = wm0 + mt * 16 + lg + ri * 8;
                #pragma unroll
                for (int nt = 0; nt < 4; nt++) {
                    float e0 = expf(s_[mt][nt][ri * 2 + 0] - m);
                    float e1 = expf(s_[mt][nt][ri * 2 + 1] - m);
                    s_[mt][nt][ri * 2 + 0] = e0;
                    s_[mt][nt][ri * 2 + 1] = e1;
                    sum += e0 + e1;
                    int c0 = wn0 + nt * 8 + 2 * lt;
                    Ps[r * 132 + c0]     = f2tf(e0);
                    Ps[r * 132 + c0 + 1] = f2tf(e1);
                    o[mt][nt][ri * 2 + 0] *= scl[mt][ri];
                    o[mt][nt][ri * 2 + 1] *= scl[mt][ri];
                }
                sum += __shfl_xor_sync(0xffffffff, sum, 1);
                sum += __shfl_xor_sync(0xffffffff, sum, 2);
                if (lt == 0) reds[r * 4 + (wid >> 1)] = sum;
            }
        }
        __syncthreads();

        #pragma unroll
        for (int mt = 0; mt < 2; mt++) {
            #pragma unroll
            for (int ri = 0; ri < 2; ri++) {
                int rl = wm0 + mt * 16 + lg + ri * 8;
                float ltile = reds[rl * 4 + 0] + reds[rl * 4 + 1]
                            + reds[rl * 4 + 2] + reds[rl * 4 + 3];
                lrow[mt][ri] = lrow[mt][ri] * scl[mt][ri] + ltile;
            }
        }

        // O += P @ V
        #pragma unroll
        for (int ks = 0; ks < 16; ks++) {
            int kb = ks * 8;
            float a[2][4], bf[4][2];
            #pragma unroll
            for (int mt = 0; mt < 2; mt++) {
                int r = wm0 + mt * 16 + lg;
                a[mt][0] = Ps[r * 132 + kb + lt];
                a[mt][1] = Ps[(r + 8) * 132 + kb + lt];
                a[mt][2] = Ps[r * 132 + kb + 4 + lt];
                a[mt][3] = Ps[(r + 8) * 132 + kb + 4 + lt];
            }
            #pragma unroll
            for (int nt = 0; nt < 4; nt++) {
                int cn = wn0 + nt * 8 + lg;
                bf[nt][0] = Vt[(kb + lt) * 136 + cn];
                bf[nt][1] = Vt[(kb + 4 + lt) * 136 + cn];
            }
            #pragma unroll
            for (int mt = 0; mt < 2; mt++)
                #pragma unroll
                for (int nt = 0; nt < 4; nt++)
                    mma1688(o[mt][nt], a[mt], bf[nt]);
        }
        __syncthreads();
    }

    // epilogue: normalize, gate, scatter into z
    #pragma unroll
    for (int mt = 0; mt < 2; mt++) {
        #pragma unroll
        for (int ri = 0; ri < 2; ri++) {
            int sglob = s0 + wm0 + mt * 16 + lg + ri * 8;
            int token = b * SS + sglob;
            int   e = g_selidx[token * NH + h];
            float g = g_selval[token * NH + h];
            float inv = g / lrow[mt][ri];
            float* zrow = g_z + ((size_t)token * NE + e) * PROJ;
            #pragma unroll
            for (int nt = 0; nt < 4; nt++) {
                int c0 = wn0 + nt * 8 + 2 * lt;
                zrow[c0]     = o[mt][nt][ri * 2 + 0] * inv;
                zrow[c0 + 1] = o[mt][nt][ri * 2 + 1] * inv;
            }
        }
    }
}

// ---------------- K1: sel = curr @ sel_dst^T, top-8, sigmoid ----------------
__global__ void sel_topk_kernel(const float* __restrict__ curr,
                                const float* __restrict__ sdst)
{
    __shared__ float srow[IN];
    __shared__ float wsum[NE][4];
    __shared__ float vals[NE];
    int bs = blockIdx.x;
    int tid = threadIdx.x;
    const float* row = curr + (long)bs * IN;
    for (int i = tid; i < IN; i += 128) srow[i] = row[i];
    __syncthreads();

    float acc[NE];
    #pragma unroll
    for (int e = 0; e < NE; e++) acc[e] = 0.f;
    for (int i = tid; i < IN; i += 128) {
        float c = srow[i];
        #pragma unroll
        for (int e = 0; e < NE; e++)
            acc[e] = fmaf(c, sdst[e*IN + i], acc[e]);
    }
    int lane = tid & 31, w = tid >> 5;
    #pragma unroll
    for (int e = 0; e < NE; e++) {
        float v = acc[e];
        #pragma unroll
        for (int o = 16; o > 0; o >>= 1) v += __shfl_xor_sync(0xffffffff, v, o);
        if (lane == 0) wsum[e][w] = v;
    }
    __syncthreads();
    if (tid < NE) vals[tid] = wsum[tid][0] + wsum[tid][1] + wsum[tid][2] + wsum[tid][3];
    __syncthreads();
    if (tid == 0) {
        bool used[NE];
        #pragma unroll
        for (int e = 0; e < NE; e++) used[e] = false;
        for (int h = 0; h < NH; h++) {
            int bi = 0; float bv = -3.4e38f;
            for (int e = 0; e < NE; e++)
                if (!used[e] && vals[e] > bv) { bv = vals[e]; bi = e; }
            used[bi] = true;
            g_selidx[bs*NH + h] = bi;
            g_selval[bs*NH + h] = 1.f / (1.f + expf(-bv));
        }
    }
}

// ---------------- kv split -> k*sc, v ---------------------------------------
__global__ void kv_split_kernel(const float* __restrict__ scalep)
{
    int t = blockIdx.x;
    int p = threadIdx.x;
    float sc = sqrtf(scalep[0]);
    g_k[(long)t*PROJ + p] = g_kv[(long)t*2*PROJ + p] * sc;
    g_v[(long)t*PROJ + p] = g_kv[(long)t*2*PROJ + PROJ + p];
}

// ---------------- sinusoidal embedding --------------------------------------
__global__ void pemb_kernel()
{
    int i = blockIdx.x;
    int tid = threadIdx.x;
    float pos = (float)i - (float)(SS - 1);
    float cst = -logf(10000.f) / (float)IN;
    for (int j = tid; j < IN/2; j += 256) {
        float dv = expf((float)(2*j) * cst);
        float s, co;
        sincosf(pos * dv, &s, &co);
        g_pemb[(long)i*IN + 2*j]     = s;
        g_pemb[(long)i*IN + 2*j + 1] = co;
    }
}

// ---------------- gather selected experts' q --------------------------------
__global__ void qgather_kernel()
{
    int s  = blockIdx.x;
    int zh = blockIdx.y;
    int b  = zh >> 3, h = zh & 7;
    int p  = threadIdx.x;
    int e  = g_selidx[((long)(b*SS) + s)*NH + h];
    g_q[((long)zh*SS + s)*PROJ + p] =
        g_qall[(((long)(b*SS + s))*NE + e)*PROJ + p];
}

// ---------------- launch ----------------------------------------------------
static float* symf(const void* sym) { void* p = nullptr; cudaGetSymbolAddress(&p, sym); return (float*)p; }

extern "C" void kernel_launch(void* const* d_in, const int* in_sizes, int n_in,
                              void* d_out, int out_size)
{
    const float* curr  = (const float*)d_in[0];
    const float* attn  = (const float*)d_in[1];
    const float* dtq   = (const float*)d_in[2];
    const float* dtkv  = (const float*)d_in[3];
    const float* oproj = (const float*)d_in[4];
    const float* ptpk  = (const float*)d_in[5];
    const float* sdst  = (const float*)d_in[6];
    const float* scale = (const float*)d_in[7];
    float* out = (float*)d_out;

    float* p_kv   = symf(g_kv);
    float* p_pemb = symf(g_pemb);
    float* p_qall = symf(g_qall);
    float* p_q    = symf(g_q);
    float* p_kpos = symf(g_kpos);
    float* p_P    = symf(g_P);
    float* p_z    = symf(g_z);

    static int smem_set = 0;
    const int FLASH_SMEM = (64*132 + 64*132 + 128*132 + 128*136 + 512) * 4;
    if (!smem_set) {
        cudaFuncSetAttribute(flash_kernel,
            cudaFuncAttributeMaxDynamicSharedMemorySize, FLASH_SMEM);
        smem_set = 1;
    }

    // expert selection
    sel_topk_kernel<<<BT, 128>>>(curr, sdst);

    // positional embedding + k_pos = pemb @ pos_to_pk^T * sc
    pemb_kernel<<<RLEN, 256>>>();
    tgemm<1><<<dim3(1, 16, 1), 256>>>(p_pemb, ptpk, p_kpos,
        RLEN, PROJ, IN, IN, IN, PROJ, 0, scale, 1, 0, 0, 0, 0, 0);

    // kv = attend_to @ data_to_kv
    tgemm<0><<<dim3(2, 32, 1), 256>>>(attn, dtkv, p_kv,
        BT, 2*PROJ, IN, IN, 2*PROJ, 2*PROJ, 0, scale, 0, 0, 0, 0, 0, 0);
    kv_split_kernel<<<BT, 128>>>(scale);

    // q_all = curr @ data_to_q (expert-packed), * sc
    tgemm<0><<<dim3(16, 32, 1), 256>>>(curr, dtq, p_qall,
        BT, NE*PROJ, IN, IN, PROJ, NE*PROJ, 1, scale, 1, 0, 0, 0, 0, 0);
    qgather_kernel<<<dim3(SS, BB*NH), 128>>>();

    // P band = Q @ kpos^T  (only the diagonal band used by shift)
    tgemm<1><<<dim3(9, 8, BB*NH), 256>>>(p_q, p_kpos, p_P,
        SS, RLEN, PROJ, PROJ, PROJ, RLEN, 0, scale, 0,
        (long)SS*PROJ, 0, (long)SS*RLEN, 0, 1);

    // fused attention: QK^T + band, softmax, @V, gate, scatter into z
    cudaMemsetAsync(p_z, 0, (size_t)BT*NE*PROJ*sizeof(float));
    flash_kernel<<<dim3(16, BB*NH), 256, FLASH_SMEM>>>();

    // output projection
    tgemm<0><<<dim3(8, 32, 1), 256>>>(p_z, oproj, out,
        BT, OUT, NE*PROJ, NE*PROJ, OUT, OUT, 2, scale, 0, 0, 0, 0, 0, 0);
}

// round 4
// speedup vs baseline: 3.3428x; 1.0984x over previous
#include <cuda_runtime.h>
#include <math.h>

#define BB 4
#define SS 1024
#define IN 1024
#define OUT 1024
#define NH 8
#define NE 16
#define PROJ 128
#define BT (BB*SS)        // 4096 tokens
#define RLEN (2*SS-1)     // 2047 relative positions

// ---------------- scratch (static device globals; allocation-free) ----------
__device__ float g_selval[BT*NH];
__device__ int   g_selidx[BT*NH];
__device__ int   g_cnt[NE];
__device__ int   g_list[NE*BT];                   // bucket lists (max 4096/expert)
__device__ float g_kv  [(size_t)BT*2*PROJ];
__device__ float g_k   [(size_t)BT*PROJ];
__device__ float g_v   [(size_t)BT*PROJ];
__device__ float g_pemb[(size_t)RLEN*IN];
__device__ float g_kpos[(size_t)RLEN*PROJ];
__device__ float g_q   [(size_t)BB*NH*SS*PROJ];
__device__ float g_P   [(size_t)BB*NH*SS*RLEN];   // band-only written
__device__ float g_z   [(size_t)BT*NE*PROJ];

// ---------------- tf32 helpers ---------------------------------------------
__device__ __forceinline__ float f2tf(float f) {
    unsigned r;
    asm("cvt.rna.tf32.f32 %0, %1;" : "=r"(r) : "f"(f));
    return __uint_as_float(r);
}

__device__ __forceinline__ void mma1688(float c[4],
                                        const float a[4], const float b[2]) {
    asm volatile(
        "mma.sync.aligned.m16n8k8.row.col.f32.tf32.tf32.f32 "
        "{%0,%1,%2,%3},{%4,%5,%6,%7},{%8,%9},{%0,%1,%2,%3};"
        : "+f"(c[0]), "+f"(c[1]), "+f"(c[2]), "+f"(c[3])
        : "r"(__float_as_uint(a[0])), "r"(__float_as_uint(a[1])),
          "r"(__float_as_uint(a[2])), "r"(__float_as_uint(a[3])),
          "r"(__float_as_uint(b[0])), "r"(__float_as_uint(b[1])));
}

// smem double-buffer geometry (dynamic)
#define AS_STRIDE 36
#define BS_STRIDE 136
#define AS_SZ (128*AS_STRIDE)          // per stage
#define BS_SZ (32*BS_STRIDE)
#define TG_SMEM ((2*(AS_SZ + BS_SZ))*4)
#define QX_SMEM (TG_SMEM + 128*4)

// ---------------- tf32 tensor-core GEMM, double-buffered, 1 sync/iter ------
// TRANSB=0: B row-major KxN (bmode 0 plain, 2 = out_proj expert blocks)
// TRANSB=1: B row-major NxK (A @ B^T). diagBand: n0 += 896 - m0.
template<int TRANSB>
__global__ __launch_bounds__(256)
void tgemm(const float* __restrict__ A, const float* __restrict__ Bm,
           float* __restrict__ C,
           int M, int N, int K, int lda, int ldb, int ldc,
           int bmode, const float* __restrict__ scalep, int alphaMode,
           long sA, long sB, long sC, int bShiftB, int diagBand)
{
    extern __shared__ float dsm[];
    float* AsBase = dsm;                 // 2 stages of 128 x AS_STRIDE
    float* BsBase = dsm + 2*AS_SZ;       // 2 stages of 32 x BS_STRIDE

    int bz = blockIdx.z;
    const float* Ap = A  + (long)bz * sA;
    const float* Bp = Bm + (long)(bz >> bShiftB) * sB;
    float*       Cp = C  + (long)bz * sC;
    int m0 = blockIdx.y * 128;
    int n0 = blockIdx.x * 128;
    if (diagBand) n0 += (896 - m0);

    int tid  = threadIdx.x;
    int wid  = tid >> 5, lane = tid & 31;
    int wm0  = (wid & 1) * 64;
    int wn0  = (wid >> 1) * 32;
    int lg   = lane >> 2;
    int lt   = lane & 3;

    float c[4][4][4];
    #pragma unroll
    for (int i = 0; i < 4; i++)
        #pragma unroll
        for (int j = 0; j < 4; j++)
            #pragma unroll
            for (int q = 0; q < 4; q++) c[i][j][q] = 0.f;

    float4 ra[4], rb[4];

    auto ldA = [&](int k0) {
        #pragma unroll
        for (int i = 0; i < 4; i++) {
            int m  = i * 32 + (tid >> 3);
            int kk = (tid & 7) * 4;
            ra[i] = make_float4(0.f, 0.f, 0.f, 0.f);
            if (m0 + m < M)
                ra[i] = *reinterpret_cast<const float4*>(Ap + (long)(m0 + m) * lda + k0 + kk);
        }
    };
    auto ldB = [&](int k0) {
        if (TRANSB == 0) {
            const float* bsrc;
            if (bmode == 0)      bsrc = Bp + (long)k0 * ldb + n0;
            else                 bsrc = Bp + (long)(k0 >> 7) * (PROJ * OUT) + (long)(k0 & 127) * OUT + n0;
            #pragma unroll
            for (int i = 0; i < 4; i++) {
                int kk = i * 8 + (tid >> 5);
                int nn = (tid & 31) * 4;
                rb[i] = *reinterpret_cast<const float4*>(bsrc + (long)kk * ldb + nn);
            }
        } else {
            #pragma unroll
            for (int i = 0; i < 4; i++) {
                int nn = i * 32 + (tid >> 3);
                int kk = (tid & 7) * 4;
                rb[i] = make_float4(0.f, 0.f, 0.f, 0.f);
                if (n0 + nn < N)
                    rb[i] = *reinterpret_cast<const float4*>(Bp + (long)(n0 + nn) * ldb + k0 + kk);
            }
        }
    };
    auto stAB = [&](int buf) {
        float* As = AsBase + buf * AS_SZ;
        float* Bs = BsBase + buf * BS_SZ;
        #pragma unroll
        for (int i = 0; i < 4; i++) {
            int m  = i * 32 + (tid >> 3);
            int kk = (tid & 7) * 4;
            float4 w = make_float4(f2tf(ra[i].x), f2tf(ra[i].y), f2tf(ra[i].z), f2tf(ra[i].w));
            *reinterpret_cast<float4*>(&As[m * AS_STRIDE + kk]) = w;
        }
        if (TRANSB == 0) {
            #pragma unroll
            for (int i = 0; i < 4; i++) {
                int kk = i * 8 + (tid >> 5);
                int nn = (tid & 31) * 4;
                float4 w = make_float4(f2tf(rb[i].x), f2tf(rb[i].y), f2tf(rb[i].z), f2tf(rb[i].w));
                *reinterpret_cast<float4*>(&Bs[kk * BS_STRIDE + nn]) = w;
            }
        } else {
            #pragma unroll
            for (int i = 0; i < 4; i++) {
                int nn = i * 32 + (tid >> 3);
                int kk = (tid & 7) * 4;
                Bs[(kk + 0) * BS_STRIDE + nn] = f2tf(rb[i].x);
                Bs[(kk + 1) * BS_STRIDE + nn] = f2tf(rb[i].y);
                Bs[(kk + 2) * BS_STRIDE + nn] = f2tf(rb[i].z);
                Bs[(kk + 3) * BS_STRIDE + nn] = f2tf(rb[i].w);
            }
        }
    };
    auto domma = [&](int buf) {
        float* As = AsBase + buf * AS_SZ;
        float* Bs = BsBase + buf * BS_SZ;
        #pragma unroll
        for (int ks = 0; ks < 4; ks++) {
            int kb = ks * 8;
            float a[4][4], b[4][2];
            #pragma unroll
            for (int mt = 0; mt < 4; mt++) {
                int r = wm0 + mt * 16 + lg;
                a[mt][0] = As[r * AS_STRIDE + kb + lt];
                a[mt][1] = As[(r + 8) * AS_STRIDE + kb + lt];
                a[mt][2] = As[r * AS_STRIDE + kb + 4 + lt];
                a[mt][3] = As[(r + 8) * AS_STRIDE + kb + 4 + lt];
            }
            #pragma unroll
            for (int nt = 0; nt < 4; nt++) {
                int cn = wn0 + nt * 8 + lg;
                b[nt][0] = Bs[(kb + lt) * BS_STRIDE + cn];
                b[nt][1] = Bs[(kb + 4 + lt) * BS_STRIDE + cn];
            }
            #pragma unroll
            for (int mt = 0; mt < 4; mt++)
                #pragma unroll
                for (int nt = 0; nt < 4; nt++)
                    mma1688(c[mt][nt], a[mt], b[nt]);
        }
    };

    int nk = K / 32;
    ldA(0); ldB(0);
    stAB(0);
    __syncthreads();
    for (int ki = 0; ki < nk; ki++) {
        if (ki + 1 < nk) { ldA((ki + 1) * 32); ldB((ki + 1) * 32); }
        domma(ki & 1);
        if (ki + 1 < nk) {
            stAB((ki + 1) & 1);
            __syncthreads();
        }
    }

    float alpha = alphaMode ? sqrtf(scalep[0]) : 1.f;
    #pragma unroll
    for (int mt = 0; mt < 4; mt++) {
        #pragma unroll
        for (int nt = 0; nt < 4; nt++) {
            int r  = m0 + wm0 + mt * 16 + lg;
            int cc = n0 + wn0 + nt * 8 + 2 * lt;
            if (r < M) {
                if (cc     < N) Cp[(long)r * ldc + cc]     = alpha * c[mt][nt][0];
                if (cc + 1 < N) Cp[(long)r * ldc + cc + 1] = alpha * c[mt][nt][1];
            }
            if (r + 8 < M) {
                if (cc     < N) Cp[(long)(r + 8) * ldc + cc]     = alpha * c[mt][nt][2];
                if (cc + 1 < N) Cp[(long)(r + 8) * ldc + cc + 1] = alpha * c[mt][nt][3];
            }
        }
    }
}

// ---------------- expert-bucketed q projection ------------------------------
// grid (1, 32, NE). Rows gathered from g_list[e]; C scattered into g_q.
__global__ __launch_bounds__(256)
void qexp_kernel(const float* __restrict__ curr, const float* __restrict__ dtq,
                 const float* __restrict__ scalep)
{
    extern __shared__ float dsm[];
    float* AsBase = dsm;
    float* BsBase = dsm + 2*AS_SZ;
    int*   ent    = (int*)(dsm + 2*(AS_SZ + BS_SZ));

    int e   = blockIdx.z;
    int cnt = g_cnt[e];
    int t0  = blockIdx.y * 128;
    if (t0 >= cnt) return;

    int tid  = threadIdx.x;
    if (tid < 128)
        ent[tid] = (t0 + tid < cnt) ? g_list[e * BT + t0 + tid] : -1;
    __syncthreads();

    const float* Bp = dtq + (size_t)e * IN * PROJ;

    int wid  = tid >> 5, lane = tid & 31;
    int wm0  = (wid & 1) * 64;
    int wn0  = (wid >> 1) * 32;
    int lg   = lane >> 2;
    int lt   = lane & 3;

    // per-thread A row tokens
    int tok4[4];
    #pragma unroll
    for (int i = 0; i < 4; i++) {
        int m = i * 32 + (tid >> 3);
        int en = ent[m];
        tok4[i] = (en >= 0) ? (en >> 3) : -1;
    }

    float c[4][4][4];
    #pragma unroll
    for (int i = 0; i < 4; i++)
        #pragma unroll
        for (int j = 0; j < 4; j++)
            #pragma unroll
            for (int q = 0; q < 4; q++) c[i][j][q] = 0.f;

    float4 ra[4], rb[4];
    auto ldA = [&](int k0) {
        int kk = (tid & 7) * 4;
        #pragma unroll
        for (int i = 0; i < 4; i++) {
            ra[i] = make_float4(0.f, 0.f, 0.f, 0.f);
            if (tok4[i] >= 0)
                ra[i] = *reinterpret_cast<const float4*>(curr + (size_t)tok4[i] * IN + k0 + kk);
        }
    };
    auto ldB = [&](int k0) {
        const float* bsrc = Bp + (size_t)k0 * PROJ;
        #pragma unroll
        for (int i = 0; i < 4; i++) {
            int kk = i * 8 + (tid >> 5);
            int nn = (tid & 31) * 4;
            rb[i] = *reinterpret_cast<const float4*>(bsrc + (size_t)kk * PROJ + nn);
        }
    };
    auto stAB = [&](int buf) {
        float* As = AsBase + buf * AS_SZ;
        float* Bs = BsBase + buf * BS_SZ;
        int kk = (tid & 7) * 4;
        #pragma unroll
        for (int i = 0; i < 4; i++) {
            int m = i * 32 + (tid >> 3);
            float4 w = make_float4(f2tf(ra[i].x), f2tf(ra[i].y), f2tf(ra[i].z), f2tf(ra[i].w));
            *reinterpret_cast<float4*>(&As[m * AS_STRIDE + kk]) = w;
        }
        #pragma unroll
        for (int i = 0; i < 4; i++) {
            int kb = i * 8 + (tid >> 5);
            int nn = (tid & 31) * 4;
            float4 w = make_float4(f2tf(rb[i].x), f2tf(rb[i].y), f2tf(rb[i].z), f2tf(rb[i].w));
            *reinterpret_cast<float4*>(&Bs[kb * BS_STRIDE + nn]) = w;
        }
    };
    auto domma = [&](int buf) {
        float* As = AsBase + buf * AS_SZ;
        float* Bs = BsBase + buf * BS_SZ;
        #pragma unroll
        for (int ks = 0; ks < 4; ks++) {
            int kb = ks * 8;
            float a[4][4], b[4][2];
            #pragma unroll
            for (int mt = 0; mt < 4; mt++) {
                int r = wm0 + mt * 16 + lg;
                a[mt][0] = As[r * AS_STRIDE + kb + lt];
                a[mt][1] = As[(r + 8) * AS_STRIDE + kb + lt];
                a[mt][2] = As[r * AS_STRIDE + kb + 4 + lt];
                a[mt][3] = As[(r + 8) * AS_STRIDE + kb + 4 + lt];
            }
            #pragma unroll
            for (int nt = 0; nt < 4; nt++) {
                int cn = wn0 + nt * 8 + lg;
                b[nt][0] = Bs[(kb + lt) * BS_STRIDE + cn];
                b[nt][1] = Bs[(kb + 4 + lt) * BS_STRIDE + cn];
            }
            #pragma unroll
            for (int mt = 0; mt < 4; mt++)
                #pragma unroll
                for (int nt = 0; nt < 4; nt++)
                    mma1688(c[mt][nt], a[mt], b[nt]);
        }
    };

    ldA(0); ldB(0);
    stAB(0);
    __syncthreads();
    for (int ki = 0; ki < 32; ki++) {
        if (ki + 1 < 32) { ldA((ki + 1) * 32); ldB((ki + 1) * 32); }
        domma(ki & 1);
        if (ki + 1 < 32) { stAB((ki + 1) & 1); __syncthreads(); }
    }

    float alpha = sqrtf(scalep[0]);
    #pragma unroll
    for (int mt = 0; mt < 4; mt++) {
        #pragma unroll
        for (int ri = 0; ri < 2; ri++) {
            int rl = wm0 + mt * 16 + lg + ri * 8;
            int en = ent[rl];
            if (en < 0) continue;
            int token = en >> 3, h = en & 7;
            int b = token >> 10, s = token & 1023;
            float* dst = g_q + ((size_t)((b * NH + h) * SS + s)) * PROJ;
            #pragma unroll
            for (int nt = 0; nt < 4; nt++) {
                int cc = wn0 + nt * 8 + 2 * lt;
                dst[cc]     = alpha * c[mt][nt][ri * 2 + 0];
                dst[cc + 1] = alpha * c[mt][nt][ri * 2 + 1];
            }
        }
    }
}

// ---------------- bucket build ----------------------------------------------
__global__ void qbucket_kernel()
{
    int i = blockIdx.x * 256 + threadIdx.x;   // 0..BT*NH-1
    if (i >= BT * NH) return;
    int e = g_selidx[i];
    int pos = atomicAdd(&g_cnt[e], 1);
    g_list[e * BT + pos] = i;
}

// ---------------- fused flash attention -------------------------------------
__global__ __launch_bounds__(256)
void flash_kernel()
{
    extern __shared__ float sm[];
    float* Qs   = sm;                    // 64 x 132
    float* Ps   = Qs + 64 * 132;         // 64 x 132
    float* Kt   = Ps + 64 * 132;         // 128 x 132
    float* Vt   = Kt + 128 * 132;        // 128 x 136
    float* redm = Vt + 128 * 136;        // 64 x 4
    float* reds = redm + 256;            // 64 x 4

    int zh = blockIdx.y;
    int b  = zh >> 3, h = zh & 7;
    int s0 = blockIdx.x * 64;
    int tid = threadIdx.x;
    int wid = tid >> 5, lane = tid & 31;
    int lg = lane >> 2, lt = lane & 3;
    int wm0 = (wid & 1) * 32;
    int wn0 = (wid >> 1) * 32;

    {
        const float* qbase = g_q + (size_t)(zh * SS + s0) * PROJ;
        #pragma unroll
        for (int it = 0; it < 8; it++) {
            int lin = it * 256 + tid;
            int r = lin >> 5, cc = (lin & 31) * 4;
            float4 v = *reinterpret_cast<const float4*>(qbase + (size_t)r * PROJ + cc);
            float4 w = make_float4(f2tf(v.x), f2tf(v.y), f2tf(v.z), f2tf(v.w));
            *reinterpret_cast<float4*>(&Qs[r * 132 + cc]) = w;
        }
    }

    float o[2][4][4];
    float mrow[2][2], lrow[2][2];
    #pragma unroll
    for (int mt = 0; mt < 2; mt++) {
        mrow[mt][0] = mrow[mt][1] = -1e30f;
        lrow[mt][0] = lrow[mt][1] = 0.f;
        #pragma unroll
        for (int nt = 0; nt < 4; nt++)
            #pragma unroll
            for (int q = 0; q < 4; q++) o[mt][nt][q] = 0.f;
    }

    for (int kt = 0; kt < 8; kt++) {
        int t0  = kt * 128;
        int bt0 = b * SS + t0;
        #pragma unroll
        for (int it = 0; it < 16; it++) {
            int lin = it * 256 + tid;
            int r = lin >> 5, cc = (lin & 31) * 4;
            float4 kv4 = *reinterpret_cast<const float4*>(g_k + (size_t)(bt0 + r) * PROJ + cc);
            float4 vv4 = *reinterpret_cast<const float4*>(g_v + (size_t)(bt0 + r) * PROJ + cc);
            *reinterpret_cast<float4*>(&Kt[r * 132 + cc]) =
                make_float4(f2tf(kv4.x), f2tf(kv4.y), f2tf(kv4.z), f2tf(kv4.w));
            *reinterpret_cast<float4*>(&Vt[r * 136 + cc]) =
                make_float4(f2tf(vv4.x), f2tf(vv4.y), f2tf(vv4.z), f2tf(vv4.w));
        }
        __syncthreads();

        float s_[2][4][4];
        #pragma unroll
        for (int mt = 0; mt < 2; mt++)
            #pragma unroll
            for (int nt = 0; nt < 4; nt++)
                #pragma unroll
                for (int q = 0; q < 4; q++) s_[mt][nt][q] = 0.f;
        #pragma unroll
        for (int ks = 0; ks < 16; ks++) {
            int kb = ks * 8;
            float a[2][4], bf[4][2];
            #pragma unroll
            for (int mt = 0; mt < 2; mt++) {
                int r = wm0 + mt * 16 + lg;
                a[mt][0] = Qs[r * 132 + kb + lt];
                a[mt][1] = Qs[(r + 8) * 132 + kb + lt];
                a[mt][2] = Qs[r * 132 + kb + 4 + lt];
                a[mt][3] = Qs[(r + 8) * 132 + kb + 4 + lt];
            }
            #pragma unroll
            for (int nt = 0; nt < 4; nt++) {
                int cn = wn0 + nt * 8 + lg;
                bf[nt][0] = Kt[cn * 132 + kb + lt];
                bf[nt][1] = Kt[cn * 132 + kb + 4 + lt];
            }
            #pragma unroll
            for (int mt = 0; mt < 2; mt++)
                #pragma unroll
                for (int nt = 0; nt < 4; nt++)
                    mma1688(s_[mt][nt], a[mt], bf[nt]);
        }

        #pragma unroll
        for (int mt = 0; mt < 2; mt++) {
            #pragma unroll
            for (int ri = 0; ri < 2; ri++) {
                int srow = s0 + wm0 + mt * 16 + lg + ri * 8;
                const float* prow = g_P + (size_t)(zh * SS + srow) * RLEN + (1023 - srow) + t0;
                #pragma unroll
                for (int nt = 0; nt < 4; nt++) {
                    int c0 = wn0 + nt * 8 + 2 * lt;
                    s_[mt][nt][ri * 2 + 0] += prow[c0];
                    s_[mt][nt][ri * 2 + 1] += prow[c0 + 1];
                }
            }
        }

        #pragma unroll
        for (int mt = 0; mt < 2; mt++) {
            #pragma unroll
            for (int ri = 0; ri < 2; ri++) {
                float v = -1e30f;
                #pragma unroll
                for (int nt = 0; nt < 4; nt++)
                    v = fmaxf(v, fmaxf(s_[mt][nt][ri * 2], s_[mt][nt][ri * 2 + 1]));
                v = fmaxf(v, __shfl_xor_sync(0xffffffff, v, 1));
                v = fmaxf(v, __shfl_xor_sync(0xffffffff, v, 2));
                if (lt == 0) {
                    int rl = wm0 + mt * 16 + lg + ri * 8;
                    redm[rl * 4 + (wid >> 1)] = v;
                }
            }
        }
        __syncthreads();

        float scl[2][2];
        #pragma unroll
        for (int mt = 0; mt < 2; mt++) {
            #pragma unroll
            for (int ri = 0; ri < 2; ri++) {
                int rl = wm0 + mt * 16 + lg + ri * 8;
                float v = fmaxf(fmaxf(redm[rl * 4 + 0], redm[rl * 4 + 1]),
                                fmaxf(redm[rl * 4 + 2], redm[rl * 4 + 3]));
                float mnew = fmaxf(mrow[mt][ri], v);
                scl[mt][ri] = expf(mrow[mt][ri] - mnew);
                mrow[mt][ri] = mnew;
            }
        }

        #pragma unroll
        for (int mt = 0; mt < 2; mt++) {
            #pragma unroll
            for (int ri = 0; ri < 2; ri++) {
                float m = mrow[mt][ri];
                float sum = 0.f;
                int r = wm0 + mt * 16 + lg + ri * 8;
                #pragma unroll
                for (int nt = 0; nt < 4; nt++) {
                    float e0 = expf(s_[mt][nt][ri * 2 + 0] - m);
                    float e1 = expf(s_[mt][nt][ri * 2 + 1] - m);
                    s_[mt][nt][ri * 2 + 0] = e0;
                    s_[mt][nt][ri * 2 + 1] = e1;
                    sum += e0 + e1;
                    int c0 = wn0 + nt * 8 + 2 * lt;
                    Ps[r * 132 + c0]     = f2tf(e0);
                    Ps[r * 132 + c0 + 1] = f2tf(e1);
                    o[mt][nt][ri * 2 + 0] *= scl[mt][ri];
                    o[mt][nt][ri * 2 + 1] *= scl[mt][ri];
                }
                sum += __shfl_xor_sync(0xffffffff, sum, 1);
                sum += __shfl_xor_sync(0xffffffff, sum, 2);
                if (lt == 0) reds[r * 4 + (wid >> 1)] = sum;
            }
        }
        __syncthreads();

        #pragma unroll
        for (int mt = 0; mt < 2; mt++) {
            #pragma unroll
            for (int ri = 0; ri < 2; ri++) {
                int rl = wm0 + mt * 16 + lg + ri * 8;
                float ltile = reds[rl * 4 + 0] + reds[rl * 4 + 1]
                            + reds[rl * 4 + 2] + reds[rl * 4 + 3];
                lrow[mt][ri] = lrow[mt][ri] * scl[mt][ri] + ltile;
            }
        }

        #pragma unroll
        for (int ks = 0; ks < 16; ks++) {
            int kb = ks * 8;
            float a[2][4], bf[4][2];
            #pragma unroll
            for (int mt = 0; mt < 2; mt++) {
                int r = wm0 + mt * 16 + lg;
                a[mt][0] = Ps[r * 132 + kb + lt];
                a[mt][1] = Ps[(r + 8) * 132 + kb + lt];
                a[mt][2] = Ps[r * 132 + kb + 4 + lt];
                a[mt][3] = Ps[(r + 8) * 132 + kb + 4 + lt];
            }
            #pragma unroll
            for (int nt = 0; nt < 4; nt++) {
                int cn = wn0 + nt * 8 + lg;
                bf[nt][0] = Vt[(kb + lt) * 136 + cn];
                bf[nt][1] = Vt[(kb + 4 + lt) * 136 + cn];
            }
            #pragma unroll
            for (int mt = 0; mt < 2; mt++)
                #pragma unroll
                for (int nt = 0; nt < 4; nt++)
                    mma1688(o[mt][nt], a[mt], bf[nt]);
        }
        __syncthreads();
    }

    #pragma unroll
    for (int mt = 0; mt < 2; mt++) {
        #pragma unroll
        for (int ri = 0; ri < 2; ri++) {
            int sglob = s0 + wm0 + mt * 16 + lg + ri * 8;
            int token = b * SS + sglob;
            int   e = g_selidx[token * NH + h];
            float g = g_selval[token * NH + h];
            float inv = g / lrow[mt][ri];
            float* zrow = g_z + ((size_t)token * NE + e) * PROJ;
            #pragma unroll
            for (int nt = 0; nt < 4; nt++) {
                int c0 = wn0 + nt * 8 + 2 * lt;
                zrow[c0]     = o[mt][nt][ri * 2 + 0] * inv;
                zrow[c0 + 1] = o[mt][nt][ri * 2 + 1] * inv;
            }
        }
    }
}

// ---------------- sel = curr @ sel_dst^T, top-8, sigmoid --------------------
__global__ void sel_topk_kernel(const float* __restrict__ curr,
                                const float* __restrict__ sdst)
{
    __shared__ float srow[IN];
    __shared__ float wsum[NE][4];
    __shared__ float vals[NE];
    int bs = blockIdx.x;
    int tid = threadIdx.x;
    const float* row = curr + (long)bs * IN;
    for (int i = tid; i < IN; i += 128) srow[i] = row[i];
    __syncthreads();

    float acc[NE];
    #pragma unroll
    for (int e = 0; e < NE; e++) acc[e] = 0.f;
    for (int i = tid; i < IN; i += 128) {
        float c = srow[i];
        #pragma unroll
        for (int e = 0; e < NE; e++)
            acc[e] = fmaf(c, sdst[e*IN + i], acc[e]);
    }
    int lane = tid & 31, w = tid >> 5;
    #pragma unroll
    for (int e = 0; e < NE; e++) {
        float v = acc[e];
        #pragma unroll
        for (int o = 16; o > 0; o >>= 1) v += __shfl_xor_sync(0xffffffff, v, o);
        if (lane == 0) wsum[e][w] = v;
    }
    __syncthreads();
    if (tid < NE) vals[tid] = wsum[tid][0] + wsum[tid][1] + wsum[tid][2] + wsum[tid][3];
    __syncthreads();
    if (tid == 0) {
        bool used[NE];
        #pragma unroll
        for (int e = 0; e < NE; e++) used[e] = false;
        for (int h = 0; h < NH; h++) {
            int bi = 0; float bv = -3.4e38f;
            for (int e = 0; e < NE; e++)
                if (!used[e] && vals[e] > bv) { bv = vals[e]; bi = e; }
            used[bi] = true;
            g_selidx[bs*NH + h] = bi;
            g_selval[bs*NH + h] = 1.f / (1.f + expf(-bv));
        }
    }
}

// ---------------- kv split -> k*sc, v ---------------------------------------
__global__ void kv_split_kernel(const float* __restrict__ scalep)
{
    int t = blockIdx.x;
    int p = threadIdx.x;
    float sc = sqrtf(scalep[0]);
    g_k[(long)t*PROJ + p] = g_kv[(long)t*2*PROJ + p] * sc;
    g_v[(long)t*PROJ + p] = g_kv[(long)t*2*PROJ + PROJ + p];
}

// ---------------- sinusoidal embedding --------------------------------------
__global__ void pemb_kernel()
{
    int i = blockIdx.x;
    int tid = threadIdx.x;
    float pos = (float)i - (float)(SS - 1);
    float cst = -logf(10000.f) / (float)IN;
    for (int j = tid; j < IN/2; j += 256) {
        float dv = expf((float)(2*j) * cst);
        float s, co;
        sincosf(pos * dv, &s, &co);
        g_pemb[(long)i*IN + 2*j]     = s;
        g_pemb[(long)i*IN + 2*j + 1] = co;
    }
}

// ---------------- launch ----------------------------------------------------
static float* symf(const void* sym) { void* p = nullptr; cudaGetSymbolAddress(&p, sym); return (float*)p; }

extern "C" void kernel_launch(void* const* d_in, const int* in_sizes, int n_in,
                              void* d_out, int out_size)
{
    const float* curr  = (const float*)d_in[0];
    const float* attn  = (const float*)d_in[1];
    const float* dtq   = (const float*)d_in[2];
    const float* dtkv  = (const float*)d_in[3];
    const float* oproj = (const float*)d_in[4];
    const float* ptpk  = (const float*)d_in[5];
    const float* sdst  = (const float*)d_in[6];
    const float* scale = (const float*)d_in[7];
    float* out = (float*)d_out;

    float* p_kv   = symf(g_kv);
    float* p_pemb = symf(g_pemb);
    float* p_kpos = symf(g_kpos);
    float* p_q    = symf(g_q);
    float* p_P    = symf(g_P);
    float* p_z    = symf(g_z);
    float* p_cnt  = symf(g_cnt);

    static int smem_set = 0;
    const int FLASH_SMEM = (64*132 + 64*132 + 128*132 + 128*136 + 512) * 4;
    if (!smem_set) {
        cudaFuncSetAttribute(flash_kernel,
            cudaFuncAttributeMaxDynamicSharedMemorySize, FLASH_SMEM);
        cudaFuncSetAttribute(tgemm<0>,
            cudaFuncAttributeMaxDynamicSharedMemorySize, TG_SMEM);
        cudaFuncSetAttribute(tgemm<1>,
            cudaFuncAttributeMaxDynamicSharedMemorySize, TG_SMEM);
        cudaFuncSetAttribute(qexp_kernel,
            cudaFuncAttributeMaxDynamicSharedMemorySize, QX_SMEM);
        smem_set = 1;
    }

    // expert selection + buckets
    sel_topk_kernel<<<BT, 128>>>(curr, sdst);
    cudaMemsetAsync(p_cnt, 0, NE * sizeof(int));
    qbucket_kernel<<<(BT*NH + 255)/256, 256>>>();

    // bucketed q projection (writes g_q directly, scaled)
    qexp_kernel<<<dim3(1, 32, NE), 256, QX_SMEM>>>(curr, dtq, scale);

    // positional embedding + k_pos = pemb @ pos_to_pk^T * sc
    pemb_kernel<<<RLEN, 256>>>();
    tgemm<1><<<dim3(1, 16, 1), 256, TG_SMEM>>>(p_pemb, ptpk, p_kpos,
        RLEN, PROJ, IN, IN, IN, PROJ, 0, scale, 1, 0, 0, 0, 0, 0);

    // kv = attend_to @ data_to_kv
    tgemm<0><<<dim3(2, 32, 1), 256, TG_SMEM>>>(attn, dtkv, p_kv,
        BT, 2*PROJ, IN, IN, 2*PROJ, 2*PROJ, 0, scale, 0, 0, 0, 0, 0, 0);
    kv_split_kernel<<<BT, 128>>>(scale);

    // P band = Q @ kpos^T  (only the diagonal band used by shift)
    tgemm<1><<<dim3(9, 8, BB*NH), 256, TG_SMEM>>>(p_q, p_kpos, p_P,
        SS, RLEN, PROJ, PROJ, PROJ, RLEN, 0, scale, 0,
        (long)SS*PROJ, 0, (long)SS*RLEN, 0, 1);

    // fused attention: QK^T + band, softmax, @V, gate, scatter into z
    cudaMemsetAsync(p_z, 0, (size_t)BT*NE*PROJ*sizeof(float));
    flash_kernel<<<dim3(16, BB*NH), 256, FLASH_SMEM>>>();

    // output projection
    tgemm<0><<<dim3(8, 32, 1), 256, TG_SMEM>>>(p_z, oproj, out,
        BT, OUT, NE*PROJ, NE*PROJ, OUT, OUT, 2, scale, 0, 0, 0, 0, 0, 0);
}